// round 8
// baseline (speedup 1.0000x reference)
#include <cuda_runtime.h>
#include <cstdint>

// Problem constants
constexpr int B_TOT = 16384;
constexpr int F = 40;
constexpr int D = 32;
constexpr int NB = 8;                  // batches per CTA
constexpr int GRID = B_TOT / NB;       // 2048
constexpr int NTHREADS = 512;          // 16 warps

// Shared strides (floats)
constexpr int HSTR  = 1284;            // h rows       (mod 32 == 4)
constexpr int HOSTR = 1604;            // hout/aggr    (mod 32 == 4, fits 40*AFS=1600)
constexpr int GSTR  = 1600;            // g rows (natural)
constexpr int AFS   = 40;              // aggr f-stride (mod 32 == 8)

// smem offsets (floats)
constexpr int OH  = 0;                      // h:   8*1284 = 10272
constexpr int OHO = OH + NB * HSTR;         // ho:  8*1604 = 12832
constexpr int OG  = OHO + NB * HOSTR;       // g:   2*1600 =  3200
constexpr int OMB = OG + 2 * GSTR;          // mbarriers (3 x u64)
constexpr int SMEM_BYTES = (OMB + 8) * 4;   // 105248 B  (2 CTAs/SM)

// W transpose scratch: [0..40) Wout_t, [40..80) Win_t, each [f][e][d]
__device__ float g_Wt[2 * 40 * 1024];

// ---------------- helpers ----------------
__device__ __forceinline__ unsigned long long pack2(float v) {
    unsigned long long r;
    asm("mov.b64 %0, {%1, %1};" : "=l"(r) : "f"(v));
    return r;
}
__device__ __forceinline__ unsigned long long ffma2(unsigned long long a,
                                                    unsigned long long b,
                                                    unsigned long long c) {
    unsigned long long d;
    asm("fma.rn.f32x2 %0, %1, %2, %3;" : "=l"(d) : "l"(a), "l"(b), "l"(c));
    return d;
}
__device__ __forceinline__ uint32_t smem_u32(const void* p) {
    return (uint32_t)__cvta_generic_to_shared(p);
}
__device__ __forceinline__ void mbar_init(uint32_t mbar, uint32_t cnt) {
    asm volatile("mbarrier.init.shared.b64 [%0], %1;" :: "r"(mbar), "r"(cnt) : "memory");
}
__device__ __forceinline__ void mbar_expect_tx(uint32_t mbar, uint32_t bytes) {
    asm volatile("mbarrier.arrive.expect_tx.shared.b64 _, [%0], %1;"
                 :: "r"(mbar), "r"(bytes) : "memory");
}
__device__ __forceinline__ void mbar_wait(uint32_t mbar, uint32_t parity) {
    uint32_t done;
    asm volatile(
        "{\n\t.reg .pred p;\n\t"
        "mbarrier.try_wait.parity.acquire.cta.shared::cta.b64 p, [%1], %2;\n\t"
        "selp.b32 %0, 1, 0, p;\n\t}"
        : "=r"(done) : "r"(mbar), "r"(parity) : "memory");
    if (!done) {
        asm volatile(
            "{\n\t.reg .pred P1;\n\t"
            "W_%=:\n\t"
            "mbarrier.try_wait.parity.acquire.cta.shared::cta.b64 P1, [%0], %1, 0x989680;\n\t"
            "@P1 bra.uni DONE_%=;\n\t"
            "bra.uni W_%=;\n\t"
            "DONE_%=:\n\t}"
            :: "r"(mbar), "r"(parity) : "memory");
    }
}
__device__ __forceinline__ void bulk_copy(uint32_t dst_smem, const void* src,
                                          uint32_t bytes, uint32_t mbar) {
    asm volatile(
        "cp.async.bulk.shared::cluster.global.mbarrier::complete_tx::bytes "
        "[%0], [%1], %2, [%3];"
        :: "r"(dst_smem), "l"(src), "r"(bytes), "r"(mbar) : "memory");
}

// ---------------- W transpose prologue ----------------
__global__ void __launch_bounds__(1024)
transposeW_kernel(const float* __restrict__ W_in, const float* __restrict__ W_out)
{
    __shared__ float t[32][33];
    const int b = blockIdx.x;                         // 0..79
    const float* src = (b < 40) ? (W_out + b * 1024) : (W_in + (b - 40) * 1024);
    float* dst = g_Wt + b * 1024;
    const int c = threadIdx.x & 31;
    const int r = threadIdx.x >> 5;
    t[r][c] = src[r * 32 + c];       // t[d][e] = W[d][e]
    __syncthreads();
    dst[r * 32 + c] = t[c][r];       // Wt[e][d] = W[d][e]
}

// ---------------- main fused kernel ----------------
__global__ void __launch_bounds__(NTHREADS, 2)
graphlayer_kernel(const float* __restrict__ g,
                  const float* __restrict__ h,
                  const float* __restrict__ bias_p,
                  float* __restrict__ out)
{
    extern __shared__ float smem[];
    float* h_s  = smem + OH;
    float* hoag = smem + OHO;
    float* g_s  = smem + OG;

    const int tid  = threadIdx.x;
    const int lane = tid & 31;
    const int warp = tid >> 5;          // 0..15
    const long b0  = (long)blockIdx.x * NB;

    const uint32_t mb_h  = smem_u32(smem + OMB);
    const uint32_t mb_g1 = mb_h + 8;
    const uint32_t mb_g2 = mb_h + 16;

    if (tid == 0) {
        mbar_init(mb_h, 1);
        mbar_init(mb_g1, 1);
        mbar_init(mb_g2, 1);
    }
    __syncthreads();

    if (tid == 0) {
        // h: 8 rows of 5120B into padded smem rows
        mbar_expect_tx(mb_h, NB * F * D * 4);
        const uint32_t hdst = smem_u32(h_s);
        #pragma unroll
        for (int j = 0; j < NB; j++)
            bulk_copy(hdst + j * HSTR * 4, h + (b0 + j) * (F * D), F * D * 4, mb_h);
        // g chunk 1 (j = 0,1)
        mbar_expect_tx(mb_g1, 2 * F * F * 4);
        const uint32_t gdst = smem_u32(g_s);
        #pragma unroll
        for (int j = 0; j < 2; j++)
            bulk_copy(gdst + j * GSTR * 4, g + (b0 + j) * (F * F), F * F * 4, mb_g1);
    }

    const float* WoutT = g_Wt;
    const float* WinT  = g_Wt + 40 * 1024;

    const int jg = lane >> 3;           // 0..3
    const int dg = lane & 7;            // 0..7 (d quad)

    mbar_wait(mb_h, 0);

    // ---------------- Stage 1: hout[j][f][d] = sum_e Wout[f][d][e] h[j][f][e] ----------------
    // 16 warps; warp does f = warp, warp+16, and (warp<8) f = warp+32.
    #pragma unroll 1
    for (int k = 0; k < 3; k++) {
        if (k == 2 && warp >= 8) break;
        const int f = (k < 2) ? (warp + 16 * k) : (32 + warp);
        const float* wt = WoutT + f * 1024 + dg * 4;
        unsigned long long acc[2][2] = {};
        #pragma unroll
        for (int e4 = 0; e4 < 8; e4++) {
            float4 hv[2];
            #pragma unroll
            for (int jt = 0; jt < 2; jt++)
                hv[jt] = *(const float4*)&h_s[(jg + 4 * jt) * HSTR + f * 32 + e4 * 4];
            #pragma unroll
            for (int ee = 0; ee < 4; ee++) {
                const ulonglong2 w2 = __ldg((const ulonglong2*)(wt + (e4 * 4 + ee) * 32));
                #pragma unroll
                for (int jt = 0; jt < 2; jt++) {
                    const unsigned long long xd = pack2(((const float*)&hv[jt])[ee]);
                    acc[jt][0] = ffma2(xd, w2.x, acc[jt][0]);
                    acc[jt][1] = ffma2(xd, w2.y, acc[jt][1]);
                }
            }
        }
        #pragma unroll
        for (int jt = 0; jt < 2; jt++)
            *(ulonglong2*)&hoag[(jg + 4 * jt) * HOSTR + f * 32 + dg * 4] =
                make_ulonglong2(acc[jt][0], acc[jt][1]);
    }
    __syncthreads();

    // prefetch g chunk 2 (j = 2..7) into the (now free) h region
    if (tid == 0) {
        mbar_expect_tx(mb_g2, 6 * F * F * 4);
        const uint32_t gdst2 = smem_u32(h_s);
        #pragma unroll
        for (int j = 0; j < 6; j++)
            bulk_copy(gdst2 + j * GSTR * 4, g + (b0 + 2 + j) * (F * F), F * F * 4, mb_g2);
    }

    // ---------------- Stage 2: aggr[j][f][d] = sum_gi g[j][f][gi] hout[j][gi][d] ----------------
    // warps 0..7: warp = batch j. lanes: fg = f group (0..3), dm = d-pair (0..7)
    if (warp < NB) {
        const int j = warp;
        if (j < 2) mbar_wait(mb_g1, 0);
        else       mbar_wait(mb_g2, 0);
        const float* gj  = (j < 2) ? (g_s + j * GSTR) : (h_s + (j - 2) * GSTR);
        float*       hob = hoag + j * HOSTR;
        const int fg = lane >> 3;
        const int dm = lane & 7;

        unsigned long long acc[10][2];
        #pragma unroll
        for (int ft = 0; ft < 10; ft++) { acc[ft][0] = 0ull; acc[ft][1] = 0ull; }

        #pragma unroll 2
        for (int gp = 0; gp < 20; gp++) {          // 2 gi per iter
            const int gi = gp * 2;
            const unsigned long long a0 = *(const unsigned long long*)(hob + gi * 32 + dm * 2);
            const unsigned long long a1 = *(const unsigned long long*)(hob + gi * 32 + dm * 2 + 16);
            const unsigned long long c0 = *(const unsigned long long*)(hob + gi * 32 + 32 + dm * 2);
            const unsigned long long c1 = *(const unsigned long long*)(hob + gi * 32 + 32 + dm * 2 + 16);
            #pragma unroll
            for (int ft = 0; ft < 10; ft++) {
                const float2 g2 = *(const float2*)(gj + (fg + 4 * ft) * F + gi);
                const unsigned long long gx = pack2(g2.x);
                const unsigned long long gy = pack2(g2.y);
                acc[ft][0] = ffma2(gx, a0, acc[ft][0]);
                acc[ft][1] = ffma2(gx, a1, acc[ft][1]);
                acc[ft][0] = ffma2(gy, c0, acc[ft][0]);
                acc[ft][1] = ffma2(gy, c1, acc[ft][1]);
            }
        }
        // write aggr in place (row j fully consumed; only this warp owns it)
        #pragma unroll
        for (int ft = 0; ft < 10; ft++) {
            const int f = fg + 4 * ft;
            *(unsigned long long*)(hob + f * AFS + dm * 2)      = acc[ft][0];
            *(unsigned long long*)(hob + f * AFS + dm * 2 + 16) = acc[ft][1];
        }
    }
    __syncthreads();

    // ---------------- Stage 3: out[j][f][d] = sum_e Win[f][d][e] aggr[j][f][e] + bias ----------------
    const float4 bias4 = __ldg((const float4*)(bias_p + dg * 4));
    const unsigned long long b2lo = *(const unsigned long long*)&bias4.x;
    const unsigned long long b2hi = *(const unsigned long long*)&bias4.z;
    #pragma unroll 1
    for (int k = 0; k < 3; k++) {
        if (k == 2 && warp >= 8) break;
        const int f = (k < 2) ? (warp + 16 * k) : (32 + warp);
        const float* wt = WinT + f * 1024 + dg * 4;
        unsigned long long acc[2][2];
        #pragma unroll
        for (int jt = 0; jt < 2; jt++) { acc[jt][0] = b2lo; acc[jt][1] = b2hi; }
        #pragma unroll
        for (int e4 = 0; e4 < 8; e4++) {
            float4 av[2];
            #pragma unroll
            for (int jt = 0; jt < 2; jt++)
                av[jt] = *(const float4*)&hoag[(jg + 4 * jt) * HOSTR + f * AFS + e4 * 4];
            #pragma unroll
            for (int ee = 0; ee < 4; ee++) {
                const ulonglong2 w2 = __ldg((const ulonglong2*)(wt + (e4 * 4 + ee) * 32));
                #pragma unroll
                for (int jt = 0; jt < 2; jt++) {
                    const unsigned long long xd = pack2(((const float*)&av[jt])[ee]);
                    acc[jt][0] = ffma2(xd, w2.x, acc[jt][0]);
                    acc[jt][1] = ffma2(xd, w2.y, acc[jt][1]);
                }
            }
        }
        #pragma unroll
        for (int jt = 0; jt < 2; jt++) {
            const int j = jg + 4 * jt;
            *(ulonglong2*)&out[(b0 + j) * (F * D) + f * 32 + dg * 4] =
                make_ulonglong2(acc[jt][0], acc[jt][1]);
        }
    }
}

extern "C" void kernel_launch(void* const* d_in, const int* in_sizes, int n_in,
                              void* d_out, int out_size)
{
    (void)in_sizes; (void)n_in; (void)out_size;
    const float* g     = (const float*)d_in[0];
    const float* h     = (const float*)d_in[1];
    const float* W_in  = (const float*)d_in[2];
    const float* W_out = (const float*)d_in[3];
    const float* bias  = (const float*)d_in[4];
    float* out = (float*)d_out;

    cudaFuncSetAttribute(graphlayer_kernel,
                         cudaFuncAttributeMaxDynamicSharedMemorySize, SMEM_BYTES);

    transposeW_kernel<<<80, 1024>>>(W_in, W_out);
    graphlayer_kernel<<<GRID, NTHREADS, SMEM_BYTES>>>(g, h, bias, out);
}

// round 9
// speedup vs baseline: 1.0781x; 1.0781x over previous
#include <cuda_runtime.h>
#include <cstdint>

// Problem constants
constexpr int B_TOT = 16384;
constexpr int F = 40;
constexpr int D = 32;
constexpr int FD = F * D;              // 1280
constexpr int FF = F * F;              // 1600
constexpr int NB = 16;                 // batches per CTA
constexpr int GRID = B_TOT / NB;       // 1024
constexpr int NTHREADS = 512;          // 16 warps

// Shared: only hout/aggr buffer.
constexpr int HOSTR = 1444;            // per-batch stride (mod 32 == 4; >= 40*AFS)
constexpr int AFS   = 36;              // aggr f-stride   (mod 32 == 4)
constexpr int SMEM_BYTES = NB * HOSTR * 4;   // 92416 B  -> 2 CTAs/SM

// W transpose scratch: [0..40) Wout_t, [40..80) Win_t, each [f][e][d]
__device__ float g_Wt[2 * 40 * 1024];

// ---------------- f32x2 helpers ----------------
__device__ __forceinline__ unsigned long long pack2(float v) {
    unsigned long long r;
    asm("mov.b64 %0, {%1, %1};" : "=l"(r) : "f"(v));
    return r;
}
__device__ __forceinline__ unsigned long long ffma2(unsigned long long a,
                                                    unsigned long long b,
                                                    unsigned long long c) {
    unsigned long long d;
    asm("fma.rn.f32x2 %0, %1, %2, %3;" : "=l"(d) : "l"(a), "l"(b), "l"(c));
    return d;
}

// ---------------- W transpose prologue ----------------
__global__ void __launch_bounds__(1024)
transposeW_kernel(const float* __restrict__ W_in, const float* __restrict__ W_out)
{
    __shared__ float t[32][33];
    const int b = blockIdx.x;                         // 0..79
    const float* src = (b < 40) ? (W_out + b * 1024) : (W_in + (b - 40) * 1024);
    float* dst = g_Wt + b * 1024;
    const int c = threadIdx.x & 31;
    const int r = threadIdx.x >> 5;
    t[r][c] = src[r * 32 + c];       // t[d][e] = W[d][e]
    __syncthreads();
    dst[r * 32 + c] = t[c][r];       // Wt[e][d] = W[d][e]
}

// ---------------- main fused kernel ----------------
__global__ void __launch_bounds__(NTHREADS, 2)
graphlayer_kernel(const float* __restrict__ g,
                  const float* __restrict__ h,
                  const float* __restrict__ bias_p,
                  float* __restrict__ out)
{
    extern __shared__ float smem[];
    float* hoag = smem;                 // [NB][HOSTR]

    const int tid  = threadIdx.x;
    const int lane = tid & 31;
    const int warp = tid >> 5;          // 0..15
    const long b0  = (long)blockIdx.x * NB;

    const float* WoutT = g_Wt;
    const float* WinT  = g_Wt + 40 * 1024;

    const int fw = warp >> 1;           // 0..7  (field group)
    const int jh = warp & 1;            // 0/1   (batch half)
    const int jg = lane >> 3;           // 0..3
    const int dg = lane & 7;            // 0..7  (d quad)

    // ---------------- Stage 1: hout[j][f][d] = sum_e Wout[f][d][e] h[j][f][e] ----------------
    // h read directly from gmem (read-once data).
    #pragma unroll 1
    for (int k = 0; k < 5; k++) {
        const int f = fw + k * 8;
        const float* wt = WoutT + f * 1024 + dg * 4;
        unsigned long long acc[2][2] = {};
        #pragma unroll
        for (int e4 = 0; e4 < 8; e4++) {
            float4 hv[2];
            #pragma unroll
            for (int jt = 0; jt < 2; jt++)
                hv[jt] = __ldg((const float4*)&h[(b0 + jg + 4 * jt + 8 * jh) * FD + f * 32 + e4 * 4]);
            #pragma unroll
            for (int ee = 0; ee < 4; ee++) {
                const ulonglong2 w2 = __ldg((const ulonglong2*)(wt + (e4 * 4 + ee) * 32));
                #pragma unroll
                for (int jt = 0; jt < 2; jt++) {
                    const unsigned long long xd = pack2(((const float*)&hv[jt])[ee]);
                    acc[jt][0] = ffma2(xd, w2.x, acc[jt][0]);
                    acc[jt][1] = ffma2(xd, w2.y, acc[jt][1]);
                }
            }
        }
        #pragma unroll
        for (int jt = 0; jt < 2; jt++)
            *(ulonglong2*)&hoag[(jg + 4 * jt + 8 * jh) * HOSTR + f * 32 + dg * 4] =
                make_ulonglong2(acc[jt][0], acc[jt][1]);
    }
    __syncthreads();

    // ---------------- Stage 2: aggr[j][f][d] = sum_gi g[j][f][gi] hout[j][gi][d] ----------------
    // warp = batch j (16 warps). g read directly from gmem (read-once data).
    {
        const int j = warp;
        const float* gj  = g + (b0 + j) * FF;
        float*       hob = hoag + j * HOSTR;
        const int fg = lane >> 3;
        const int dm = lane & 7;

        unsigned long long acc[10][2];
        #pragma unroll
        for (int ft = 0; ft < 10; ft++) { acc[ft][0] = 0ull; acc[ft][1] = 0ull; }

        #pragma unroll 2
        for (int gp = 0; gp < 20; gp++) {          // 2 gi per iter
            const int gi = gp * 2;
            const unsigned long long a0 = *(const unsigned long long*)(hob + gi * 32 + dm * 2);
            const unsigned long long a1 = *(const unsigned long long*)(hob + gi * 32 + dm * 2 + 16);
            const unsigned long long c0 = *(const unsigned long long*)(hob + gi * 32 + 32 + dm * 2);
            const unsigned long long c1 = *(const unsigned long long*)(hob + gi * 32 + 32 + dm * 2 + 16);
            #pragma unroll
            for (int ft = 0; ft < 10; ft++) {
                const float2 g2 = __ldg((const float2*)(gj + (fg + 4 * ft) * F + gi));
                const unsigned long long gx = pack2(g2.x);
                const unsigned long long gy = pack2(g2.y);
                acc[ft][0] = ffma2(gx, a0, acc[ft][0]);
                acc[ft][1] = ffma2(gx, a1, acc[ft][1]);
                acc[ft][0] = ffma2(gy, c0, acc[ft][0]);
                acc[ft][1] = ffma2(gy, c1, acc[ft][1]);
            }
        }
        // write aggr in place (row j fully consumed; only this warp owns it)
        #pragma unroll
        for (int ft = 0; ft < 10; ft++) {
            const int f = fg + 4 * ft;
            *(unsigned long long*)(hob + f * AFS + dm * 2)      = acc[ft][0];
            *(unsigned long long*)(hob + f * AFS + dm * 2 + 16) = acc[ft][1];
        }
    }
    __syncthreads();

    // ---------------- Stage 3: out[j][f][d] = sum_e Win[f][d][e] aggr[j][f][e] + bias ----------------
    const float4 bias4 = __ldg((const float4*)(bias_p + dg * 4));
    const unsigned long long b2lo = *(const unsigned long long*)&bias4.x;
    const unsigned long long b2hi = *(const unsigned long long*)&bias4.z;
    #pragma unroll 1
    for (int k = 0; k < 5; k++) {
        const int f = fw + k * 8;
        const float* wt = WinT + f * 1024 + dg * 4;
        unsigned long long acc[2][2];
        #pragma unroll
        for (int jt = 0; jt < 2; jt++) { acc[jt][0] = b2lo; acc[jt][1] = b2hi; }
        #pragma unroll
        for (int e4 = 0; e4 < 8; e4++) {
            float4 av[2];
            #pragma unroll
            for (int jt = 0; jt < 2; jt++)
                av[jt] = *(const float4*)&hoag[(jg + 4 * jt + 8 * jh) * HOSTR + f * AFS + e4 * 4];
            #pragma unroll
            for (int ee = 0; ee < 4; ee++) {
                const ulonglong2 w2 = __ldg((const ulonglong2*)(wt + (e4 * 4 + ee) * 32));
                #pragma unroll
                for (int jt = 0; jt < 2; jt++) {
                    const unsigned long long xd = pack2(((const float*)&av[jt])[ee]);
                    acc[jt][0] = ffma2(xd, w2.x, acc[jt][0]);
                    acc[jt][1] = ffma2(xd, w2.y, acc[jt][1]);
                }
            }
        }
        #pragma unroll
        for (int jt = 0; jt < 2; jt++) {
            const int j = jg + 4 * jt + 8 * jh;
            *(ulonglong2*)&out[(b0 + j) * FD + f * 32 + dg * 4] =
                make_ulonglong2(acc[jt][0], acc[jt][1]);
        }
    }
}

extern "C" void kernel_launch(void* const* d_in, const int* in_sizes, int n_in,
                              void* d_out, int out_size)
{
    (void)in_sizes; (void)n_in; (void)out_size;
    const float* g     = (const float*)d_in[0];
    const float* h     = (const float*)d_in[1];
    const float* W_in  = (const float*)d_in[2];
    const float* W_out = (const float*)d_in[3];
    const float* bias  = (const float*)d_in[4];
    float* out = (float*)d_out;

    cudaFuncSetAttribute(graphlayer_kernel,
                         cudaFuncAttributeMaxDynamicSharedMemorySize, SMEM_BYTES);

    transposeW_kernel<<<80, 1024>>>(W_in, W_out);
    graphlayer_kernel<<<GRID, NTHREADS, SMEM_BYTES>>>(g, h, bias, out);
}

// round 10
// speedup vs baseline: 1.1029x; 1.0230x over previous
#include <cuda_runtime.h>
#include <cstdint>

// Problem constants
constexpr int B_TOT = 16384;
constexpr int F = 40;
constexpr int D = 32;
constexpr int FD = F * D;              // 1280
constexpr int FF = F * F;              // 1600
constexpr int NB = 16;                 // batches per CTA
constexpr int GRID = B_TOT / NB;       // 1024
constexpr int NTHREADS = 512;          // 16 warps

// Single shared buffer, reused in place: h -> hout -> aggr
constexpr int HOSTR = 1444;            // per-batch stride (mod 32 == 4; >= 40*AFS)
constexpr int AFS   = 36;              // aggr f-stride (mod 32 == 4, 16B-aligned)
constexpr int OMB   = NB * HOSTR;      // mbarrier offset (floats)
constexpr int SMEM_BYTES = (OMB + 4) * 4;   // 92432 B -> 2 CTAs/SM

// W transpose scratch: [0..40) Wout_t, [40..80) Win_t, each [f][e][d]
__device__ float g_Wt[2 * 40 * 1024];

// ---------------- f32x2 helpers ----------------
__device__ __forceinline__ unsigned long long pack2(float v) {
    unsigned long long r;
    asm("mov.b64 %0, {%1, %1};" : "=l"(r) : "f"(v));
    return r;
}
__device__ __forceinline__ unsigned long long ffma2(unsigned long long a,
                                                    unsigned long long b,
                                                    unsigned long long c) {
    unsigned long long d;
    asm("fma.rn.f32x2 %0, %1, %2, %3;" : "=l"(d) : "l"(a), "l"(b), "l"(c));
    return d;
}
__device__ __forceinline__ uint32_t smem_u32(const void* p) {
    return (uint32_t)__cvta_generic_to_shared(p);
}
__device__ __forceinline__ void mbar_init(uint32_t mbar, uint32_t cnt) {
    asm volatile("mbarrier.init.shared.b64 [%0], %1;" :: "r"(mbar), "r"(cnt) : "memory");
}
__device__ __forceinline__ void mbar_expect_tx(uint32_t mbar, uint32_t bytes) {
    asm volatile("mbarrier.arrive.expect_tx.shared.b64 _, [%0], %1;"
                 :: "r"(mbar), "r"(bytes) : "memory");
}
__device__ __forceinline__ void mbar_wait(uint32_t mbar, uint32_t parity) {
    uint32_t done;
    asm volatile(
        "{\n\t.reg .pred p;\n\t"
        "mbarrier.try_wait.parity.acquire.cta.shared::cta.b64 p, [%1], %2;\n\t"
        "selp.b32 %0, 1, 0, p;\n\t}"
        : "=r"(done) : "r"(mbar), "r"(parity) : "memory");
    if (!done) {
        asm volatile(
            "{\n\t.reg .pred P1;\n\t"
            "W_%=:\n\t"
            "mbarrier.try_wait.parity.acquire.cta.shared::cta.b64 P1, [%0], %1, 0x989680;\n\t"
            "@P1 bra.uni DONE_%=;\n\t"
            "bra.uni W_%=;\n\t"
            "DONE_%=:\n\t}"
            :: "r"(mbar), "r"(parity) : "memory");
    }
}
__device__ __forceinline__ void bulk_copy(uint32_t dst_smem, const void* src,
                                          uint32_t bytes, uint32_t mbar) {
    asm volatile(
        "cp.async.bulk.shared::cluster.global.mbarrier::complete_tx::bytes "
        "[%0], [%1], %2, [%3];"
        :: "r"(dst_smem), "l"(src), "r"(bytes), "r"(mbar) : "memory");
}

// ---------------- W transpose prologue ----------------
__global__ void __launch_bounds__(1024)
transposeW_kernel(const float* __restrict__ W_in, const float* __restrict__ W_out)
{
    __shared__ float t[32][33];
    const int b = blockIdx.x;                         // 0..79
    const float* src = (b < 40) ? (W_out + b * 1024) : (W_in + (b - 40) * 1024);
    float* dst = g_Wt + b * 1024;
    const int c = threadIdx.x & 31;
    const int r = threadIdx.x >> 5;
    t[r][c] = src[r * 32 + c];       // t[d][e] = W[d][e]
    __syncthreads();
    dst[r * 32 + c] = t[c][r];       // Wt[e][d] = W[d][e]
}

// ---------------- main fused kernel ----------------
__global__ void __launch_bounds__(NTHREADS, 2)
graphlayer_kernel(const float* __restrict__ g,
                  const float* __restrict__ h,
                  const float* __restrict__ bias_p,
                  float* __restrict__ out)
{
    extern __shared__ float smem[];
    float* buf = smem;                  // [NB][HOSTR]: h -> hout -> aggr (in place)

    const int tid  = threadIdx.x;
    const int lane = tid & 31;
    const int warp = tid >> 5;          // 0..15
    const long b0  = (long)blockIdx.x * NB;

    const uint32_t mb_h = smem_u32(smem + OMB);
    if (tid == 0) mbar_init(mb_h, 1);
    __syncthreads();

    if (tid == 0) {
        mbar_expect_tx(mb_h, NB * FD * 4);
        const uint32_t hdst = smem_u32(buf);
        #pragma unroll
        for (int j = 0; j < NB; j++)
            bulk_copy(hdst + j * HOSTR * 4, h + (b0 + j) * FD, FD * 4, mb_h);
    }

    const float* WoutT = g_Wt;
    const float* WinT  = g_Wt + 40 * 1024;

    const int jg = lane >> 3;           // 0..3
    const int dg = lane & 7;            // 0..7 (d quad)

    mbar_wait(mb_h, 0);

    // ---------------- Stage 1 (in place): hout[j][f][d] = sum_e Wout[f][d][e] h[j][f][e]
    // warp owns field f exclusively (4j x 4d thread tile covers all 16 batches).
    #pragma unroll 1
    for (int k = 0; k < 3; k++) {
        if (k == 2 && warp >= 8) break;
        const int f = (k < 2) ? (warp + 16 * k) : (32 + warp);
        const float* wt = WoutT + f * 1024 + dg * 4;
        unsigned long long acc[4][2] = {};
        #pragma unroll
        for (int e4 = 0; e4 < 8; e4++) {
            float4 hv[4];
            #pragma unroll
            for (int jt = 0; jt < 4; jt++)
                hv[jt] = *(const float4*)&buf[(jg + 4 * jt) * HOSTR + f * 32 + e4 * 4];
            #pragma unroll
            for (int ee = 0; ee < 4; ee++) {
                const ulonglong2 w2 = __ldg((const ulonglong2*)(wt + (e4 * 4 + ee) * 32));
                #pragma unroll
                for (int jt = 0; jt < 4; jt++) {
                    const unsigned long long xd = pack2(((const float*)&hv[jt])[ee]);
                    acc[jt][0] = ffma2(xd, w2.x, acc[jt][0]);
                    acc[jt][1] = ffma2(xd, w2.y, acc[jt][1]);
                }
            }
        }
        // overwrite h with hout (this warp is the only reader/writer of column f)
        #pragma unroll
        for (int jt = 0; jt < 4; jt++)
            *(ulonglong2*)&buf[(jg + 4 * jt) * HOSTR + f * 32 + dg * 4] =
                make_ulonglong2(acc[jt][0], acc[jt][1]);
    }
    __syncthreads();

    // ---------------- Stage 2 (in place): aggr[j][f][d] = sum_gi g[j][f][gi] hout[j][gi][d]
    // warp = batch j; g read directly from gmem (read-once, 10-way MLP per gi).
    {
        const float* gj  = g + (b0 + warp) * FF;
        float*       hob = buf + warp * HOSTR;
        const int fg = lane >> 3;
        const int dm = lane & 7;

        unsigned long long acc[10][2];
        #pragma unroll
        for (int ft = 0; ft < 10; ft++) { acc[ft][0] = 0ull; acc[ft][1] = 0ull; }

        #pragma unroll 2
        for (int gi = 0; gi < F; gi++) {
            const unsigned long long a0 = *(const unsigned long long*)(hob + gi * 32 + dm * 2);
            const unsigned long long a1 = *(const unsigned long long*)(hob + gi * 32 + dm * 2 + 16);
            #pragma unroll
            for (int ft = 0; ft < 10; ft++) {
                const unsigned long long gx = pack2(__ldg(gj + (fg + 4 * ft) * F + gi));
                acc[ft][0] = ffma2(gx, a0, acc[ft][0]);
                acc[ft][1] = ffma2(gx, a1, acc[ft][1]);
            }
        }
        // write aggr in place (row fully consumed; only this warp owns it)
        #pragma unroll
        for (int ft = 0; ft < 10; ft++) {
            const int f = fg + 4 * ft;
            *(unsigned long long*)(hob + f * AFS + dm * 2)      = acc[ft][0];
            *(unsigned long long*)(hob + f * AFS + dm * 2 + 16) = acc[ft][1];
        }
    }
    __syncthreads();

    // ---------------- Stage 3: out[j][f][d] = sum_e Win[f][d][e] aggr[j][f][e] + bias
    const float4 bias4 = __ldg((const float4*)(bias_p + dg * 4));
    const unsigned long long b2lo = *(const unsigned long long*)&bias4.x;
    const unsigned long long b2hi = *(const unsigned long long*)&bias4.z;
    #pragma unroll 1
    for (int k = 0; k < 3; k++) {
        if (k == 2 && warp >= 8) break;
        const int f = (k < 2) ? (warp + 16 * k) : (32 + warp);
        const float* wt = WinT + f * 1024 + dg * 4;
        unsigned long long acc[4][2];
        #pragma unroll
        for (int jt = 0; jt < 4; jt++) { acc[jt][0] = b2lo; acc[jt][1] = b2hi; }
        #pragma unroll
        for (int e4 = 0; e4 < 8; e4++) {
            float4 av[4];
            #pragma unroll
            for (int jt = 0; jt < 4; jt++)
                av[jt] = *(const float4*)&buf[(jg + 4 * jt) * HOSTR + f * AFS + e4 * 4];
            #pragma unroll
            for (int ee = 0; ee < 4; ee++) {
                const ulonglong2 w2 = __ldg((const ulonglong2*)(wt + (e4 * 4 + ee) * 32));
                #pragma unroll
                for (int jt = 0; jt < 4; jt++) {
                    const unsigned long long xd = pack2(((const float*)&av[jt])[ee]);
                    acc[jt][0] = ffma2(xd, w2.x, acc[jt][0]);
                    acc[jt][1] = ffma2(xd, w2.y, acc[jt][1]);
                }
            }
        }
        #pragma unroll
        for (int jt = 0; jt < 4; jt++) {
            const int j = jg + 4 * jt;
            *(ulonglong2*)&out[(b0 + j) * FD + f * 32 + dg * 4] =
                make_ulonglong2(acc[jt][0], acc[jt][1]);
        }
    }
}

extern "C" void kernel_launch(void* const* d_in, const int* in_sizes, int n_in,
                              void* d_out, int out_size)
{
    (void)in_sizes; (void)n_in; (void)out_size;
    const float* g     = (const float*)d_in[0];
    const float* h     = (const float*)d_in[1];
    const float* W_in  = (const float*)d_in[2];
    const float* W_out = (const float*)d_in[3];
    const float* bias  = (const float*)d_in[4];
    float* out = (float*)d_out;

    cudaFuncSetAttribute(graphlayer_kernel,
                         cudaFuncAttributeMaxDynamicSharedMemorySize, SMEM_BYTES);

    transposeW_kernel<<<80, 1024>>>(W_in, W_out);
    graphlayer_kernel<<<GRID, NTHREADS, SMEM_BYTES>>>(g, h, bias, out);
}

// round 11
// speedup vs baseline: 1.1039x; 1.0009x over previous
#include <cuda_runtime.h>
#include <cstdint>

typedef unsigned long long ull;

// Problem constants
constexpr int B_TOT = 16384;
constexpr int F = 40;
constexpr int D = 32;
constexpr int FD = F * D;              // 1280
constexpr int FF = F * F;              // 1600
constexpr int NB = 16;                 // batches per CTA
constexpr int GRID = B_TOT / NB;       // 1024
constexpr int NTHREADS = 1024;         // 32 warps

// Shared layout
constexpr int HSTR = 1444;             // buffer row stride (h -> hout -> aggr), mod 32 == 4
constexpr int AFS  = 36;               // aggr f-stride (fits: 39*36+32 < 1444)
constexpr int OG   = NB * HSTR;        // 23104: g region [16][1600]
constexpr int OMB  = OG + NB * FF;     // 48704: mbarriers
constexpr int SMEM_BYTES = (OMB + 4) * 4;   // 194832 B (1 CTA/SM)

// W transpose scratch: [0..40) Wout_t, [40..80) Win_t, each [f][e][d]
__device__ float g_Wt[2 * 40 * 1024];

// ---------------- f32x2 helpers ----------------
__device__ __forceinline__ ull pack2(float v) {
    ull r;
    asm("mov.b64 %0, {%1, %1};" : "=l"(r) : "f"(v));
    return r;
}
__device__ __forceinline__ ull ffma2(ull a, ull b, ull c) {
    ull d;
    asm("fma.rn.f32x2 %0, %1, %2, %3;" : "=l"(d) : "l"(a), "l"(b), "l"(c));
    return d;
}
__device__ __forceinline__ uint32_t smem_u32(const void* p) {
    return (uint32_t)__cvta_generic_to_shared(p);
}
__device__ __forceinline__ void mbar_init(uint32_t mbar, uint32_t cnt) {
    asm volatile("mbarrier.init.shared.b64 [%0], %1;" :: "r"(mbar), "r"(cnt) : "memory");
}
__device__ __forceinline__ void mbar_expect_tx(uint32_t mbar, uint32_t bytes) {
    asm volatile("mbarrier.arrive.expect_tx.shared.b64 _, [%0], %1;"
                 :: "r"(mbar), "r"(bytes) : "memory");
}
__device__ __forceinline__ void mbar_wait(uint32_t mbar, uint32_t parity) {
    uint32_t done;
    asm volatile(
        "{\n\t.reg .pred p;\n\t"
        "mbarrier.try_wait.parity.acquire.cta.shared::cta.b64 p, [%1], %2;\n\t"
        "selp.b32 %0, 1, 0, p;\n\t}"
        : "=r"(done) : "r"(mbar), "r"(parity) : "memory");
    if (!done) {
        asm volatile(
            "{\n\t.reg .pred P1;\n\t"
            "W_%=:\n\t"
            "mbarrier.try_wait.parity.acquire.cta.shared::cta.b64 P1, [%0], %1, 0x989680;\n\t"
            "@P1 bra.uni DONE_%=;\n\t"
            "bra.uni W_%=;\n\t"
            "DONE_%=:\n\t}"
            :: "r"(mbar), "r"(parity) : "memory");
    }
}
__device__ __forceinline__ void bulk_copy(uint32_t dst_smem, const void* src,
                                          uint32_t bytes, uint32_t mbar) {
    asm volatile(
        "cp.async.bulk.shared::cluster.global.mbarrier::complete_tx::bytes "
        "[%0], [%1], %2, [%3];"
        :: "r"(dst_smem), "l"(src), "r"(bytes), "r"(mbar) : "memory");
}

// ---------------- W transpose prologue ----------------
__global__ void __launch_bounds__(1024)
transposeW_kernel(const float* __restrict__ W_in, const float* __restrict__ W_out)
{
    __shared__ float t[32][33];
    const int b = blockIdx.x;                         // 0..79
    const float* src = (b < 40) ? (W_out + b * 1024) : (W_in + (b - 40) * 1024);
    float* dst = g_Wt + b * 1024;
    const int c = threadIdx.x & 31;
    const int r = threadIdx.x >> 5;
    t[r][c] = src[r * 32 + c];       // t[d][e] = W[d][e]
    __syncthreads();
    dst[r * 32 + c] = t[c][r];       // Wt[e][d] = W[d][e]
}

// ---------------- main fused kernel ----------------
__global__ void __launch_bounds__(NTHREADS, 1)
graphlayer_kernel(const float* __restrict__ g,
                  const float* __restrict__ h,
                  const float* __restrict__ bias_p,
                  float* __restrict__ out)
{
    extern __shared__ float smem[];
    float* buf = smem;                  // [NB][HSTR]: h -> hout -> aggr (in place)
    float* g_s = smem + OG;             // [NB][FF]

    const int tid  = threadIdx.x;
    const int lane = tid & 31;
    const int warp = tid >> 5;          // 0..31
    const long b0  = (long)blockIdx.x * NB;

    const uint32_t mb_h = smem_u32(smem + OMB);
    const uint32_t mb_g = mb_h + 8;

    if (tid == 0) { mbar_init(mb_h, 1); mbar_init(mb_g, 1); }
    __syncthreads();

    if (tid == 0) {
        mbar_expect_tx(mb_h, NB * FD * 4);
        const uint32_t hdst = smem_u32(buf);
        #pragma unroll
        for (int j = 0; j < NB; j++)
            bulk_copy(hdst + j * HSTR * 4, h + (b0 + j) * FD, FD * 4, mb_h);
        mbar_expect_tx(mb_g, NB * FF * 4);
        const uint32_t gdst = smem_u32(g_s);
        #pragma unroll
        for (int j = 0; j < NB; j++)
            bulk_copy(gdst + j * FF * 4, g + (b0 + j) * FF, FF * 4, mb_g);
    }

    const float* WoutT = g_Wt;
    const float* WinT  = g_Wt + 40 * 1024;

    const int jg = lane >> 3;           // 0..3
    const int dg = lane & 7;            // 0..7 (d quad)

    mbar_wait(mb_h, 0);

    // ---------------- Stage 1 (in place): hout[j][f][d] = sum_e Wout[f][d][e] h[j][f][e]
    // 80 units = (f: 40) x (j-half: 2); warp w takes units w, w+32, w+64(<80).
    #pragma unroll 1
    for (int pass = 0; pass < 3; pass++) {
        const int u = warp + pass * 32;
        if (u >= 80) break;
        const int f  = u >> 1;
        const int jb = (u & 1) * 8 + jg * 2;        // this lane's 2 batches: jb, jb+1
        const float* wt = WoutT + f * 1024 + dg * 4;
        ull acc[2][2] = {};
        #pragma unroll
        for (int e4 = 0; e4 < 8; e4++) {
            const float4 hv0 = *(const float4*)&buf[jb * HSTR + f * 32 + e4 * 4];
            const float4 hv1 = *(const float4*)&buf[(jb + 1) * HSTR + f * 32 + e4 * 4];
            #pragma unroll
            for (int ee = 0; ee < 4; ee++) {
                const ulonglong2 w2 = __ldg((const ulonglong2*)(wt + (e4 * 4 + ee) * 32));
                const ull x0 = pack2(((const float*)&hv0)[ee]);
                const ull x1 = pack2(((const float*)&hv1)[ee]);
                acc[0][0] = ffma2(x0, w2.x, acc[0][0]);
                acc[0][1] = ffma2(x0, w2.y, acc[0][1]);
                acc[1][0] = ffma2(x1, w2.x, acc[1][0]);
                acc[1][1] = ffma2(x1, w2.y, acc[1][1]);
            }
        }
        // overwrite h with hout (stores after all reads of this (f, j) slice)
        *(ulonglong2*)&buf[jb * HSTR + f * 32 + dg * 4] =
            make_ulonglong2(acc[0][0], acc[0][1]);
        *(ulonglong2*)&buf[(jb + 1) * HSTR + f * 32 + dg * 4] =
            make_ulonglong2(acc[1][0], acc[1][1]);
    }
    __syncthreads();

    // ---------------- Stage 2 (in place): aggr[j][f][d] = sum_gi g[j][f][gi] hout[j][gi][d]
    // warp = batch j (warps 0..15); g fully staged in smem.
    if (warp < NB) {
        mbar_wait(mb_g, 0);
        const float* gj  = g_s + warp * FF;
        float*       hob = buf + warp * HSTR;
        const int fg = lane >> 3;       // 0..3
        const int dm = lane & 7;        // 0..7 (d pairs: dm*2 and dm*2+16)

        ull acc[10][2];
        #pragma unroll
        for (int ft = 0; ft < 10; ft++) { acc[ft][0] = 0ull; acc[ft][1] = 0ull; }

        #pragma unroll 2
        for (int gp = 0; gp < 20; gp++) {          // 2 gi per iter
            const int gi = gp * 2;
            const ull a0 = *(const ull*)(hob + gi * 32 + dm * 2);
            const ull a1 = *(const ull*)(hob + gi * 32 + dm * 2 + 16);
            const ull c0 = *(const ull*)(hob + gi * 32 + 32 + dm * 2);
            const ull c1 = *(const ull*)(hob + gi * 32 + 32 + dm * 2 + 16);
            #pragma unroll
            for (int ft = 0; ft < 10; ft++) {
                const float2 g2 = *(const float2*)(gj + (fg + 4 * ft) * F + gi);
                const ull gx = pack2(g2.x);
                const ull gy = pack2(g2.y);
                acc[ft][0] = ffma2(gx, a0, acc[ft][0]);
                acc[ft][1] = ffma2(gx, a1, acc[ft][1]);
                acc[ft][0] = ffma2(gy, c0, acc[ft][0]);
                acc[ft][1] = ffma2(gy, c1, acc[ft][1]);
            }
        }
        // write aggr in place (row fully consumed; this warp owns the whole row)
        #pragma unroll
        for (int ft = 0; ft < 10; ft++) {
            const int f = fg + 4 * ft;
            *(ull*)(hob + f * AFS + dm * 2)      = acc[ft][0];
            *(ull*)(hob + f * AFS + dm * 2 + 16) = acc[ft][1];
        }
    }
    __syncthreads();

    // ---------------- Stage 3: out[j][f][d] = sum_e Win[f][d][e] aggr[j][f][e] + bias
    const float4 bias4 = __ldg((const float4*)(bias_p + dg * 4));
    const ull b2lo = *(const ull*)&bias4.x;
    const ull b2hi = *(const ull*)&bias4.z;
    #pragma unroll 1
    for (int pass = 0; pass < 3; pass++) {
        const int u = warp + pass * 32;
        if (u >= 80) break;
        const int f  = u >> 1;
        const int jb = (u & 1) * 8 + jg * 2;
        const float* wt = WinT + f * 1024 + dg * 4;
        ull acc[2][2] = {{b2lo, b2hi}, {b2lo, b2hi}};
        #pragma unroll
        for (int e4 = 0; e4 < 8; e4++) {
            const float4 av0 = *(const float4*)&buf[jb * HSTR + f * AFS + e4 * 4];
            const float4 av1 = *(const float4*)&buf[(jb + 1) * HSTR + f * AFS + e4 * 4];
            #pragma unroll
            for (int ee = 0; ee < 4; ee++) {
                const ulonglong2 w2 = __ldg((const ulonglong2*)(wt + (e4 * 4 + ee) * 32));
                const ull x0 = pack2(((const float*)&av0)[ee]);
                const ull x1 = pack2(((const float*)&av1)[ee]);
                acc[0][0] = ffma2(x0, w2.x, acc[0][0]);
                acc[0][1] = ffma2(x0, w2.y, acc[0][1]);
                acc[1][0] = ffma2(x1, w2.x, acc[1][0]);
                acc[1][1] = ffma2(x1, w2.y, acc[1][1]);
            }
        }
        *(ulonglong2*)&out[(b0 + jb) * FD + f * 32 + dg * 4] =
            make_ulonglong2(acc[0][0], acc[0][1]);
        *(ulonglong2*)&out[(b0 + jb + 1) * FD + f * 32 + dg * 4] =
            make_ulonglong2(acc[1][0], acc[1][1]);
    }
}

extern "C" void kernel_launch(void* const* d_in, const int* in_sizes, int n_in,
                              void* d_out, int out_size)
{
    (void)in_sizes; (void)n_in; (void)out_size;
    const float* g     = (const float*)d_in[0];
    const float* h     = (const float*)d_in[1];
    const float* W_in  = (const float*)d_in[2];
    const float* W_out = (const float*)d_in[3];
    const float* bias  = (const float*)d_in[4];
    float* out = (float*)d_out;

    cudaFuncSetAttribute(graphlayer_kernel,
                         cudaFuncAttributeMaxDynamicSharedMemorySize, SMEM_BYTES);

    transposeW_kernel<<<80, 1024>>>(W_in, W_out);
    graphlayer_kernel<<<GRID, NTHREADS, SMEM_BYTES>>>(g, h, bias, out);
}

// round 12
// speedup vs baseline: 1.4068x; 1.2744x over previous
#include <cuda_runtime.h>
#include <cstdint>

typedef unsigned long long ull;

// Problem constants
constexpr int B_TOT = 16384;
constexpr int F = 40;
constexpr int D = 32;
constexpr int NB = 16;                 // batches per CTA
constexpr int GRID = B_TOT / NB;       // 1024
constexpr int NTHREADS = 768;          // 24 warps

// Shared strides (floats)
constexpr int HSTR  = 1284;            // h rows       (mod 32 == 4)
constexpr int HOSTR = 1444;            // hout/aggr    (mod 32 == 4)
constexpr int GSTR  = 1600;            // g rows (natural)
constexpr int AFS   = 36;              // aggr f-stride (mod 32 == 4)

// smem offsets (floats)
constexpr int OH  = 0;                     // h:    16*1284 = 20544
constexpr int OHO = OH + NB * HSTR;        // ho:   16*1444 = 23104
constexpr int OG  = OHO + NB * HOSTR;      // g:     8*1600 = 12800
constexpr int OMB = OG + 8 * GSTR;         // mbarriers (3 x u64)
constexpr int SMEM_BYTES = (OMB + 8) * 4;  // 225824 B

// W transpose scratch: [0..40) Wout_t, [40..80) Win_t, each [f][e][d]
__device__ float g_Wt[2 * 40 * 1024];

// ---------------- helpers ----------------
__device__ __forceinline__ ull pack2(float v) {
    ull r;
    asm("mov.b64 %0, {%1, %1};" : "=l"(r) : "f"(v));
    return r;
}
__device__ __forceinline__ ull ffma2(ull a, ull b, ull c) {
    ull d;
    asm("fma.rn.f32x2 %0, %1, %2, %3;" : "=l"(d) : "l"(a), "l"(b), "l"(c));
    return d;
}
__device__ __forceinline__ uint32_t smem_u32(const void* p) {
    return (uint32_t)__cvta_generic_to_shared(p);
}
__device__ __forceinline__ void mbar_init(uint32_t mbar, uint32_t cnt) {
    asm volatile("mbarrier.init.shared.b64 [%0], %1;" :: "r"(mbar), "r"(cnt) : "memory");
}
__device__ __forceinline__ void mbar_expect_tx(uint32_t mbar, uint32_t bytes) {
    asm volatile("mbarrier.arrive.expect_tx.shared.b64 _, [%0], %1;"
                 :: "r"(mbar), "r"(bytes) : "memory");
}
__device__ __forceinline__ void mbar_wait(uint32_t mbar, uint32_t parity) {
    uint32_t done;
    asm volatile(
        "{\n\t.reg .pred p;\n\t"
        "mbarrier.try_wait.parity.acquire.cta.shared::cta.b64 p, [%1], %2;\n\t"
        "selp.b32 %0, 1, 0, p;\n\t}"
        : "=r"(done) : "r"(mbar), "r"(parity) : "memory");
    if (!done) {
        asm volatile(
            "{\n\t.reg .pred P1;\n\t"
            "W_%=:\n\t"
            "mbarrier.try_wait.parity.acquire.cta.shared::cta.b64 P1, [%0], %1, 0x989680;\n\t"
            "@P1 bra.uni DONE_%=;\n\t"
            "bra.uni W_%=;\n\t"
            "DONE_%=:\n\t}"
            :: "r"(mbar), "r"(parity) : "memory");
    }
}
__device__ __forceinline__ void bulk_copy(uint32_t dst_smem, const void* src,
                                          uint32_t bytes, uint32_t mbar) {
    asm volatile(
        "cp.async.bulk.shared::cluster.global.mbarrier::complete_tx::bytes "
        "[%0], [%1], %2, [%3];"
        :: "r"(dst_smem), "l"(src), "r"(bytes), "r"(mbar) : "memory");
}

// ---------------- W transpose prologue ----------------
__global__ void __launch_bounds__(1024)
transposeW_kernel(const float* __restrict__ W_in, const float* __restrict__ W_out)
{
    __shared__ float t[32][33];
    const int b = blockIdx.x;                         // 0..79
    const float* src = (b < 40) ? (W_out + b * 1024) : (W_in + (b - 40) * 1024);
    float* dst = g_Wt + b * 1024;
    const int c = threadIdx.x & 31;
    const int r = threadIdx.x >> 5;
    t[r][c] = src[r * 32 + c];       // t[d][e] = W[d][e]
    __syncthreads();
    dst[r * 32 + c] = t[c][r];       // Wt[e][d] = W[d][e]
}

// ---------------- main fused kernel ----------------
__global__ void __launch_bounds__(NTHREADS, 1)
graphlayer_kernel(const float* __restrict__ g,
                  const float* __restrict__ h,
                  const float* __restrict__ bias_p,
                  float* __restrict__ out)
{
    extern __shared__ float smem[];
    float* h_s  = smem + OH;
    float* hoag = smem + OHO;
    float* g_s  = smem + OG;

    const int tid  = threadIdx.x;
    const int lane = tid & 31;
    const int warp = tid >> 5;          // 0..23
    const long b0  = (long)blockIdx.x * NB;

    const uint32_t mb_h  = smem_u32(smem + OMB);
    const uint32_t mb_g1 = mb_h + 8;
    const uint32_t mb_g2 = mb_h + 16;

    if (tid == 0) {
        mbar_init(mb_h, 1);
        mbar_init(mb_g1, 1);
        mbar_init(mb_g2, 1);
    }
    __syncthreads();

    if (tid == 0) {
        // h: 16 rows of 5120B into padded smem rows
        mbar_expect_tx(mb_h, NB * F * D * 4);
        const uint32_t hdst = smem_u32(h_s);
        #pragma unroll
        for (int j = 0; j < NB; j++)
            bulk_copy(hdst + j * HSTR * 4, h + (b0 + j) * (F * D), F * D * 4, mb_h);
        // g chunk 1 (j = 0..7)
        mbar_expect_tx(mb_g1, 8 * F * F * 4);
        const uint32_t gdst = smem_u32(g_s);
        #pragma unroll
        for (int j = 0; j < 8; j++)
            bulk_copy(gdst + j * GSTR * 4, g + (b0 + j) * (F * F), F * F * 4, mb_g1);
    }

    const float* WoutT = g_Wt;
    const float* WinT  = g_Wt + 40 * 1024;

    const int jg = lane >> 3;           // 0..3
    const int dg = lane & 7;            // 0..7 (d quad)

    mbar_wait(mb_h, 0);

    // ---------------- Stage 1: hout[j][f][d] = sum_e Wout[f][d][e] h[j][f][e] ----------------
    // 80 units = (f: 40) x (j-half: 2), striped over 24 warps.
    #pragma unroll 1
    for (int u = warp; u < 80; u += 24) {
        const int f  = u >> 1;
        const int jh = u & 1;
        const float* wt = WoutT + f * 1024 + dg * 4;
        ull acc[2][2] = {};
        #pragma unroll
        for (int e4 = 0; e4 < 8; e4++) {
            float4 hv[2];
            #pragma unroll
            for (int jt = 0; jt < 2; jt++)
                hv[jt] = *(const float4*)&h_s[(jg + 4 * jt + 8 * jh) * HSTR + f * 32 + e4 * 4];
            #pragma unroll
            for (int ee = 0; ee < 4; ee++) {
                const ulonglong2 w2 = __ldg((const ulonglong2*)(wt + (e4 * 4 + ee) * 32));
                #pragma unroll
                for (int jt = 0; jt < 2; jt++) {
                    const ull xd = pack2(((const float*)&hv[jt])[ee]);
                    acc[jt][0] = ffma2(xd, w2.x, acc[jt][0]);
                    acc[jt][1] = ffma2(xd, w2.y, acc[jt][1]);
                }
            }
        }
        #pragma unroll
        for (int jt = 0; jt < 2; jt++)
            *(ulonglong2*)&hoag[(jg + 4 * jt + 8 * jh) * HOSTR + f * 32 + dg * 4] =
                make_ulonglong2(acc[jt][0], acc[jt][1]);
    }
    __syncthreads();

    // prefetch g chunk 2 (j = 8..15) into the (now free) h region
    if (tid == 0) {
        mbar_expect_tx(mb_g2, 8 * F * F * 4);
        const uint32_t gdst2 = smem_u32(h_s);
        #pragma unroll
        for (int j = 0; j < 8; j++)
            bulk_copy(gdst2 + j * GSTR * 4, g + (b0 + 8 + j) * (F * F), F * F * 4, mb_g2);
    }

    // ---------------- Stage 2: aggr[j][f][d] = sum_gi g[j][f][gi] hout[j][gi][d] ----------------
    // warps 0..15: warp = batch j. lanes: fg = f group (0..3), dm = d-pair (0..7)
    if (warp < NB) {
        const int j = warp;
        if (j < 8) mbar_wait(mb_g1, 0);
        else       mbar_wait(mb_g2, 0);
        const float* gj  = (j < 8) ? (g_s + j * GSTR) : (h_s + (j - 8) * GSTR);
        float*       hob = hoag + j * HOSTR;
        const int fg = lane >> 3;
        const int dm = lane & 7;

        ull acc[10][2];
        #pragma unroll
        for (int ft = 0; ft < 10; ft++) { acc[ft][0] = 0ull; acc[ft][1] = 0ull; }

        #pragma unroll 2
        for (int gp = 0; gp < 10; gp++) {          // 4 gi per iter
            ull ho0[4], ho1[4];
            #pragma unroll
            for (int t = 0; t < 4; t++) {
                ho0[t] = *(const ull*)(hob + (gp * 4 + t) * 32 + dm * 2);
                ho1[t] = *(const ull*)(hob + (gp * 4 + t) * 32 + dm * 2 + 16);
            }
            #pragma unroll
            for (int ft = 0; ft < 10; ft++) {
                const float4 g4 = *(const float4*)(gj + (fg + 4 * ft) * F + gp * 4);
                acc[ft][0] = ffma2(pack2(g4.x), ho0[0], acc[ft][0]);
                acc[ft][1] = ffma2(pack2(g4.x), ho1[0], acc[ft][1]);
                acc[ft][0] = ffma2(pack2(g4.y), ho0[1], acc[ft][0]);
                acc[ft][1] = ffma2(pack2(g4.y), ho1[1], acc[ft][1]);
                acc[ft][0] = ffma2(pack2(g4.z), ho0[2], acc[ft][0]);
                acc[ft][1] = ffma2(pack2(g4.z), ho1[2], acc[ft][1]);
                acc[ft][0] = ffma2(pack2(g4.w), ho0[3], acc[ft][0]);
                acc[ft][1] = ffma2(pack2(g4.w), ho1[3], acc[ft][1]);
            }
        }
        // write aggr in place (row j fully consumed; only this warp owns it)
        #pragma unroll
        for (int ft = 0; ft < 10; ft++) {
            const int f = fg + 4 * ft;
            *(ull*)(hob + f * AFS + dm * 2)      = acc[ft][0];
            *(ull*)(hob + f * AFS + dm * 2 + 16) = acc[ft][1];
        }
    }
    __syncthreads();

    // ---------------- Stage 3: out[j][f][d] = sum_e Win[f][d][e] aggr[j][f][e] + bias ----------------
    const float4 bias4 = __ldg((const float4*)(bias_p + dg * 4));
    const ull b2lo = *(const ull*)&bias4.x;
    const ull b2hi = *(const ull*)&bias4.z;
    #pragma unroll 1
    for (int u = warp; u < 80; u += 24) {
        const int f  = u >> 1;
        const int jh = u & 1;
        const float* wt = WinT + f * 1024 + dg * 4;
        ull acc[2][2] = {{b2lo, b2hi}, {b2lo, b2hi}};
        #pragma unroll
        for (int e4 = 0; e4 < 8; e4++) {
            float4 av[2];
            #pragma unroll
            for (int jt = 0; jt < 2; jt++)
                av[jt] = *(const float4*)&hoag[(jg + 4 * jt + 8 * jh) * HOSTR + f * AFS + e4 * 4];
            #pragma unroll
            for (int ee = 0; ee < 4; ee++) {
                const ulonglong2 w2 = __ldg((const ulonglong2*)(wt + (e4 * 4 + ee) * 32));
                #pragma unroll
                for (int jt = 0; jt < 2; jt++) {
                    const ull xd = pack2(((const float*)&av[jt])[ee]);
                    acc[jt][0] = ffma2(xd, w2.x, acc[jt][0]);
                    acc[jt][1] = ffma2(xd, w2.y, acc[jt][1]);
                }
            }
        }
        #pragma unroll
        for (int jt = 0; jt < 2; jt++) {
            const int j = jg + 4 * jt + 8 * jh;
            *(ulonglong2*)&out[(b0 + j) * (F * D) + f * 32 + dg * 4] =
                make_ulonglong2(acc[jt][0], acc[jt][1]);
        }
    }
}

extern "C" void kernel_launch(void* const* d_in, const int* in_sizes, int n_in,
                              void* d_out, int out_size)
{
    (void)in_sizes; (void)n_in; (void)out_size;
    const float* g     = (const float*)d_in[0];
    const float* h     = (const float*)d_in[1];
    const float* W_in  = (const float*)d_in[2];
    const float* W_out = (const float*)d_in[3];
    const float* bias  = (const float*)d_in[4];
    float* out = (float*)d_out;

    cudaFuncSetAttribute(graphlayer_kernel,
                         cudaFuncAttributeMaxDynamicSharedMemorySize, SMEM_BYTES);

    transposeW_kernel<<<80, 1024>>>(W_in, W_out);
    graphlayer_kernel<<<GRID, NTHREADS, SMEM_BYTES>>>(g, h, bias, out);
}